// round 7
// baseline (speedup 1.0000x reference)
#include <cuda_runtime.h>
#include <cuda_bf16.h>
#include <cstdint>

// Problem constants
#define BB   2
#define SS   2048
#define DIM  2048
#define NH   16
#define DH   128
#define LKV  512
#define LQ   1024
#define MR   (BB*SS)    // 4096
#define HD   (NH*DH)    // 2048

// Static scratch
__device__ float g_cq [MR*(size_t)LQ];
__device__ float g_ckv[MR*(size_t)LKV];
__device__ float g_qr [MR*(size_t)HD];     // fp32 (pre-rope)
__device__ float g_kr [MR*(size_t)HD];     // fp32 (pre-rope)
__device__ float g_v  [MR*(size_t)HD];     // fp32
__device__ float g_att[MR*(size_t)HD];
// bf16 hi/lo split operand buffers for the flash kernel
__device__ __nv_bfloat16 g_qa_h[MR*(size_t)HD], g_qa_l[MR*(size_t)HD];
__device__ __nv_bfloat16 g_qr_h[MR*(size_t)HD], g_qr_l[MR*(size_t)HD];
__device__ __nv_bfloat16 g_ka_h[MR*(size_t)HD], g_ka_l[MR*(size_t)HD];
__device__ __nv_bfloat16 g_kr_h[MR*(size_t)HD], g_kr_l[MR*(size_t)HD];
__device__ __nv_bfloat16 g_vt_h[(size_t)BB*NH*DH*SS], g_vt_l[(size_t)BB*NH*DH*SS];

// ---------------------------------------------------------------------------
// Helpers
// ---------------------------------------------------------------------------
__device__ __forceinline__ uint32_t smem_u32(const void* p) {
    uint32_t a;
    asm("{ .reg .u64 t; cvta.to.shared.u64 t, %1; cvt.u32.u64 %0, t; }" : "=r"(a) : "l"(p));
    return a;
}

__device__ __forceinline__ void ldm_x4(uint32_t addr, uint32_t r[4]) {
    asm volatile("ldmatrix.sync.aligned.m8n8.x4.shared.b16 {%0,%1,%2,%3}, [%4];"
                 : "=r"(r[0]), "=r"(r[1]), "=r"(r[2]), "=r"(r[3]) : "r"(addr));
}

__device__ __forceinline__ void mma16816(float c[4], const uint32_t a[4],
                                         uint32_t b0, uint32_t b1) {
    asm volatile(
        "mma.sync.aligned.m16n8k16.row.col.f32.bf16.bf16.f32 "
        "{%0,%1,%2,%3}, {%4,%5,%6,%7}, {%8,%9}, {%0,%1,%2,%3};"
        : "+f"(c[0]), "+f"(c[1]), "+f"(c[2]), "+f"(c[3])
        : "r"(a[0]), "r"(a[1]), "r"(a[2]), "r"(a[3]), "r"(b0), "r"(b1));
}

__device__ __forceinline__ uint32_t packbf(float a, float b) {
    uint32_t r;
    asm("cvt.rn.satfinite.bf16x2.f32 %0, %1, %2;" : "=r"(r) : "f"(b), "f"(a));
    return r;
}
__device__ __forceinline__ float lo_of(uint32_t h) { return __uint_as_float(h << 16); }
__device__ __forceinline__ float hi_of(uint32_t h) { return __uint_as_float(h & 0xFFFF0000u); }

__device__ __forceinline__ void sts_v4(uint32_t addr, uint4 v) {
    asm volatile("st.shared.v4.b32 [%0], {%1,%2,%3,%4};"
                 :: "r"(addr), "r"(v.x), "r"(v.y), "r"(v.z), "r"(v.w) : "memory");
}
__device__ __forceinline__ void sts_u32(uint32_t addr, uint32_t v) {
    asm volatile("st.shared.b32 [%0], %1;" :: "r"(addr), "r"(v) : "memory");
}
__device__ __forceinline__ void cp16(uint32_t dst, const void* src) {
    asm volatile("cp.async.cg.shared.global [%0], [%1], 16;" :: "r"(dst), "l"(src) : "memory");
}
#define CP_COMMIT asm volatile("cp.async.commit_group;" ::: "memory")
#define CP_WAIT0  asm volatile("cp.async.wait_group 0;" ::: "memory")
#define CP_WAIT1  asm volatile("cp.async.wait_group 1;" ::: "memory")

// SMEM layout for tgemm (per stage): A_hi, A_lo, B_hi, B_lo, 128 rows x 80B
#define PITCH    80
#define OF_ALO   10240
#define OF_BHI   20480
#define OF_BLO   30720
#define STAGE_SZ 40960
#define SMEMSZ   81920

// ---------------------------------------------------------------------------
// Warp-MMA GEMM (proven round-3 config): C = alpha * A * B^T [+ bias]
// SPLITOUT: write bf16 hi/lo arrays instead of fp32 C.
// ---------------------------------------------------------------------------
template<bool BIAS, bool DUAL, bool SPLITOUT>
__global__ __launch_bounds__(512)
void tgemm(int K,
           const float* __restrict__ A, int lda, long long sAb, long long sAh,
           const float* __restrict__ Bm, int ldb, long long sBb, long long sBh,
           const float* __restrict__ A2, const float* __restrict__ B2,
           float* __restrict__ C, int ldc, long long sCb, long long sCh,
           const float* __restrict__ bias, float alpha, int Hdiv,
           __nv_bfloat16* __restrict__ Chi, __nv_bfloat16* __restrict__ Clo)
{
    extern __shared__ __align__(128) char smc[];
    const uint32_t smb = smem_u32(smc);
    const int tid  = threadIdx.x;
    const int lane = tid & 31;
    const int wid  = tid >> 5;
    const int wm   = (wid & 3) * 32;
    const int wn   = (wid >> 2) * 32;

    int z = blockIdx.z;
    int zb = z / Hdiv, zh = z - zb * Hdiv;
    A  += zb * sAb + zh * sAh;
    Bm += zb * sBb + zh * sBh;
    if (DUAL) { A2 += zb * sAb + zh * sAh; B2 += zb * sBb + zh * sBh; }
    C  += zb * sCb + zh * sCh;

    const int arow = tid >> 2;
    const int ako  = (tid & 3) * 8;
    const long long aoff = (long long)(blockIdx.y * 128 + arow) * lda;
    const long long boff = (long long)(blockIdx.x * 128 + arow) * ldb;

    float acc[2][4][4];
#pragma unroll
    for (int i = 0; i < 2; i++)
#pragma unroll
        for (int j = 0; j < 4; j++)
#pragma unroll
            for (int k = 0; k < 4; k++) acc[i][j][k] = 0.f;

    const int nch   = K >> 5;
    const int total = DUAL ? nch * 2 : nch;

    float4 ra0, ra1, rb0, rb1;

    auto LDG = [&](int c) {
        const float* Ap = A; const float* Bp = Bm; int cc = c;
        if (DUAL && c >= nch) { Ap = A2; Bp = B2; cc = c - nch; }
        const float* pa = Ap + aoff + cc * 32 + ako;
        const float* pb = Bp + boff + cc * 32 + ako;
        ra0 = *(const float4*)pa; ra1 = *(const float4*)(pa + 4);
        rb0 = *(const float4*)pb; rb1 = *(const float4*)(pb + 4);
    };

    auto STS = [&](int s) {
        const uint32_t base = smb + s * STAGE_SZ + arow * PITCH + ako * 2;
        uint4 hi, lo;
        hi.x = packbf(ra0.x, ra0.y); hi.y = packbf(ra0.z, ra0.w);
        hi.z = packbf(ra1.x, ra1.y); hi.w = packbf(ra1.z, ra1.w);
        lo.x = packbf(ra0.x - lo_of(hi.x), ra0.y - hi_of(hi.x));
        lo.y = packbf(ra0.z - lo_of(hi.y), ra0.w - hi_of(hi.y));
        lo.z = packbf(ra1.x - lo_of(hi.z), ra1.y - hi_of(hi.z));
        lo.w = packbf(ra1.z - lo_of(hi.w), ra1.w - hi_of(hi.w));
        sts_v4(base, hi);
        sts_v4(base + OF_ALO, lo);
        hi.x = packbf(rb0.x, rb0.y); hi.y = packbf(rb0.z, rb0.w);
        hi.z = packbf(rb1.x, rb1.y); hi.w = packbf(rb1.z, rb1.w);
        lo.x = packbf(rb0.x - lo_of(hi.x), rb0.y - hi_of(hi.x));
        lo.y = packbf(rb0.z - lo_of(hi.y), rb0.w - hi_of(hi.y));
        lo.z = packbf(rb1.x - lo_of(hi.z), rb1.y - hi_of(hi.z));
        lo.w = packbf(rb1.z - lo_of(hi.w), rb1.w - hi_of(hi.w));
        sts_v4(base + OF_BHI, hi);
        sts_v4(base + OF_BLO, lo);
    };

    auto COMPUTE = [&](int s) {
        const uint32_t sa = smb + s * STAGE_SZ;
#pragma unroll
        for (int ks = 0; ks < 2; ++ks) {
            const uint32_t colb = ks * 32;
            uint32_t ahi[2][4], alo[2][4], bhi[2][4], blo[2][4];
#pragma unroll
            for (int mt = 0; mt < 2; ++mt) {
                uint32_t addr = sa +
                    (wm + mt * 16 + (lane & 15)) * PITCH + colb + (lane >> 4) * 16;
                ldm_x4(addr, ahi[mt]);
                ldm_x4(addr + OF_ALO, alo[mt]);
            }
#pragma unroll
            for (int np = 0; np < 2; ++np) {
                uint32_t addr = sa + OF_BHI +
                    (wn + np * 16 + (lane & 7) + ((lane >> 4) << 3)) * PITCH +
                    colb + ((lane >> 3) & 1) * 16;
                ldm_x4(addr, bhi[np]);
                ldm_x4(addr + (OF_BLO - OF_BHI), blo[np]);
            }
#pragma unroll
            for (int mt = 0; mt < 2; ++mt)
#pragma unroll
                for (int nt = 0; nt < 4; ++nt) {
                    uint32_t b0h = bhi[nt >> 1][(nt & 1) * 2];
                    uint32_t b1h = bhi[nt >> 1][(nt & 1) * 2 + 1];
                    uint32_t b0l = blo[nt >> 1][(nt & 1) * 2];
                    uint32_t b1l = blo[nt >> 1][(nt & 1) * 2 + 1];
                    mma16816(acc[mt][nt], ahi[mt], b0h, b1h);
                    mma16816(acc[mt][nt], ahi[mt], b0l, b1l);
                    mma16816(acc[mt][nt], alo[mt], b0h, b1h);
                }
        }
    };

    LDG(0);
    STS(0);
    __syncthreads();
    for (int c = 0; c < total; ++c) {
        if (c + 1 < total) LDG(c + 1);
        COMPUTE(c & 1);
        if (c + 1 < total) STS((c + 1) & 1);
        __syncthreads();
    }

    const int g = lane >> 2, t = lane & 3;
#pragma unroll
    for (int mt = 0; mt < 2; ++mt) {
        const int r0 = blockIdx.y * 128 + wm + mt * 16 + g;
#pragma unroll
        for (int nt = 0; nt < 4; ++nt) {
            const int col = blockIdx.x * 128 + wn + nt * 8 + t * 2;
            float b0 = 0.f, b1 = 0.f;
            if (BIAS) { b0 = bias[col]; b1 = bias[col + 1]; }
            float2 v0, v1;
            v0.x = alpha * acc[mt][nt][0] + b0;
            v0.y = alpha * acc[mt][nt][1] + b1;
            v1.x = alpha * acc[mt][nt][2] + b0;
            v1.y = alpha * acc[mt][nt][3] + b1;
            if (SPLITOUT) {
                uint32_t h0 = packbf(v0.x, v0.y);
                uint32_t l0 = packbf(v0.x - lo_of(h0), v0.y - hi_of(h0));
                uint32_t h1 = packbf(v1.x, v1.y);
                uint32_t l1 = packbf(v1.x - lo_of(h1), v1.y - hi_of(h1));
                *(uint32_t*)&Chi[(long long)r0 * ldc + col] = h0;
                *(uint32_t*)&Clo[(long long)r0 * ldc + col] = l0;
                *(uint32_t*)&Chi[(long long)(r0 + 8) * ldc + col] = h1;
                *(uint32_t*)&Clo[(long long)(r0 + 8) * ldc + col] = l1;
            } else {
                *(float2*)&C[(long long)r0 * ldc + col] = v0;
                *(float2*)&C[(long long)(r0 + 8) * ldc + col] = v1;
            }
        }
    }
}

// ---------------------------------------------------------------------------
// RoPE + split: read fp32, rotate, write bf16 hi/lo
// ---------------------------------------------------------------------------
__global__ void rope_split(const float* __restrict__ src,
                           __nv_bfloat16* __restrict__ dh,
                           __nv_bfloat16* __restrict__ dl,
                           const float* __restrict__ fc,
                           const float* __restrict__ fs)
{
    long long idx = (long long)blockIdx.x * blockDim.x + threadIdx.x;
    const long long total = (long long)MR * NH * (DH / 2);
    if (idx >= total) return;
    int i = (int)(idx & 63);
    long long t2 = idx >> 6;
    int h = (int)(t2 % NH);
    long long row = t2 / NH;
    int s = (int)(row % SS);
    float c  = fc[s * 64 + i];
    float sn = fs[s * 64 + i];
    size_t off = (size_t)row * HD + h * DH + 2 * i;
    float e = src[off], o = src[off + 1];
    float e2 = e * c - o * sn;
    float o2 = e * sn + o * c;
    uint32_t hi = packbf(e2, o2);
    uint32_t lo = packbf(e2 - lo_of(hi), o2 - hi_of(hi));
    *(uint32_t*)&dh[off] = hi;
    *(uint32_t*)&dl[off] = lo;
}

// ---------------------------------------------------------------------------
// Transpose V + split: vt[(z)*DH + d][s] = v[(b*SS+s)*HD + h*DH + d], bf16 hi/lo
// ---------------------------------------------------------------------------
__global__ void transpose_split(const float* __restrict__ v,
                                __nv_bfloat16* __restrict__ vth,
                                __nv_bfloat16* __restrict__ vtl)
{
    __shared__ float t[32][33];
    int z = blockIdx.z;
    int b = z / NH, h = z - b * NH;
    int s0 = blockIdx.y * 32, d0 = blockIdx.x * 32;
    int x = threadIdx.x, y = threadIdx.y;
#pragma unroll
    for (int i = 0; i < 32; i += 8)
        t[y + i][x] = v[((long long)(b * SS + s0 + y + i)) * HD + h * DH + d0 + x];
    __syncthreads();
#pragma unroll
    for (int i = 0; i < 32; i += 8) {
        float val = t[x][y + i];
        __nv_bfloat16 hb = __float2bfloat16(val);
        __nv_bfloat16 lb = __float2bfloat16(val - __bfloat162float(hb));
        size_t off = ((size_t)(z * DH + d0 + y + i)) * SS + s0 + x;
        vth[off] = hb;
        vtl[off] = lb;
    }
}

// ---------------------------------------------------------------------------
// Fused flash attention: per CTA = one (q-tile of 128, z=(b,h)).
// S = scale*(Qa Ka^T + Qr Kr^T) per 128-k-block, online softmax, O += P V.
// All operands pre-split bf16 hi/lo; 3-product emulation throughout.
// Grid (SS/128, BB*NH), 512 threads.
// ---------------------------------------------------------------------------
#define F_STAGE   40960                  // S staging stage size (A/B hi/lo, pitch 80)
#define F_PHI     81920                  // P hi tile, pitch 272
#define F_PLO_OF  34816                  // P lo offset from PHI
#define F_PITCHP  272
#define F_REDM    151552                 // 128 x 4 floats
#define F_REDS    153600                 // 128 x 4 floats
#define F_SMEM    155648

__global__ __launch_bounds__(512, 1)
void flash_attn(const __nv_bfloat16* __restrict__ qah, const __nv_bfloat16* __restrict__ qal,
                const __nv_bfloat16* __restrict__ qrh, const __nv_bfloat16* __restrict__ qrl,
                const __nv_bfloat16* __restrict__ kah, const __nv_bfloat16* __restrict__ kal,
                const __nv_bfloat16* __restrict__ krh, const __nv_bfloat16* __restrict__ krl,
                const __nv_bfloat16* __restrict__ vth, const __nv_bfloat16* __restrict__ vtl,
                float* __restrict__ att, float scale)
{
    extern __shared__ __align__(128) char smc[];
    const uint32_t smb = smem_u32(smc);
    float* redM = (float*)(smc + F_REDM);
    float* redS = (float*)(smc + F_REDS);

    const int tid  = threadIdx.x;
    const int lane = tid & 31;
    const int wid  = tid >> 5;
    const int wm   = (wid & 3) * 32;
    const int wn   = (wid >> 2) * 32;
    const int wcol = wid >> 2;
    const int g    = lane >> 2;
    const int t    = lane & 3;

    const int z  = blockIdx.y;
    const int b  = z / NH, h = z - b * NH;
    const int q0 = blockIdx.x * 128;

    const int srow = tid >> 2;            // staging row 0..127
    const int scg  = (tid & 3) * 8;       // staging col group (bf16 elems)
    const size_t qbase = ((size_t)(b * SS) + q0 + srow) * HD + h * DH + scg;

    float oacc[2][4][4];
    float m[2][2], l[2][2];
#pragma unroll
    for (int i = 0; i < 2; i++) {
#pragma unroll
        for (int j = 0; j < 4; j++)
#pragma unroll
            for (int k = 0; k < 4; k++) oacc[i][j][k] = 0.f;
        m[i][0] = -1e30f; m[i][1] = -1e30f;
        l[i][0] = 0.f;    l[i][1] = 0.f;
    }

    for (int kb = 0; kb < SS / 128; ++kb) {
        float sacc[2][4][4];
#pragma unroll
        for (int i = 0; i < 2; i++)
#pragma unroll
            for (int j = 0; j < 4; j++)
#pragma unroll
                for (int k = 0; k < 4; k++) sacc[i][j][k] = 0.f;

        const size_t kbase = ((size_t)(b * SS) + kb * 128 + srow) * HD + h * DH + scg;

        // ---- S phase: 8 chunks of 32 (qa·ka for c<4, qr·kr for c>=4) ----
        auto issueS = [&](int c) {
            const __nv_bfloat16 *qh, *ql, *kh, *kl;
            if (c < 4) { qh = qah; ql = qal; kh = kah; kl = kal; }
            else       { qh = qrh; ql = qrl; kh = krh; kl = krl; }
            const int d0 = (c & 3) * 32;
            const uint32_t dst = smb + (c & 1) * F_STAGE + srow * PITCH + scg * 2;
            cp16(dst,            qh + qbase + d0);
            cp16(dst + OF_ALO,   ql + qbase + d0);
            cp16(dst + OF_BHI,   kh + kbase + d0);
            cp16(dst + OF_BLO,   kl + kbase + d0);
        };

        auto COMPUTE_S = [&](int s) {
            const uint32_t sa = smb + s * F_STAGE;
#pragma unroll
            for (int ks = 0; ks < 2; ++ks) {
                const uint32_t colb = ks * 32;
                uint32_t ahi[2][4], alo[2][4], bhi[2][4], blo[2][4];
#pragma unroll
                for (int mt = 0; mt < 2; ++mt) {
                    uint32_t addr = sa +
                        (wm + mt * 16 + (lane & 15)) * PITCH + colb + (lane >> 4) * 16;
                    ldm_x4(addr, ahi[mt]);
                    ldm_x4(addr + OF_ALO, alo[mt]);
                }
#pragma unroll
                for (int np = 0; np < 2; ++np) {
                    uint32_t addr = sa + OF_BHI +
                        (wn + np * 16 + (lane & 7) + ((lane >> 4) << 3)) * PITCH +
                        colb + ((lane >> 3) & 1) * 16;
                    ldm_x4(addr, bhi[np]);
                    ldm_x4(addr + (OF_BLO - OF_BHI), blo[np]);
                }
#pragma unroll
                for (int mt = 0; mt < 2; ++mt)
#pragma unroll
                    for (int nt = 0; nt < 4; ++nt) {
                        uint32_t b0h = bhi[nt >> 1][(nt & 1) * 2];
                        uint32_t b1h = bhi[nt >> 1][(nt & 1) * 2 + 1];
                        uint32_t b0l = blo[nt >> 1][(nt & 1) * 2];
                        uint32_t b1l = blo[nt >> 1][(nt & 1) * 2 + 1];
                        mma16816(sacc[mt][nt], ahi[mt], b0h, b1h);
                        mma16816(sacc[mt][nt], ahi[mt], b0l, b1l);
                        mma16816(sacc[mt][nt], alo[mt], b0h, b1h);
                    }
            }
        };

        issueS(0); CP_COMMIT;
        for (int c = 0; c < 8; ++c) {
            if (c < 7) { issueS(c + 1); CP_COMMIT; CP_WAIT1; } else { CP_WAIT0; }
            __syncthreads();
            COMPUTE_S(c & 1);
            __syncthreads();
        }

        // ---- online softmax update ----
        // per-thread partial row max
        float pm[2][2];
#pragma unroll
        for (int mt = 0; mt < 2; ++mt)
#pragma unroll
            for (int hf = 0; hf < 2; ++hf) {
                float v = sacc[mt][0][hf * 2];
#pragma unroll
                for (int nt = 0; nt < 4; ++nt) {
                    v = fmaxf(v, sacc[mt][nt][hf * 2]);
                    v = fmaxf(v, sacc[mt][nt][hf * 2 + 1]);
                }
#pragma unroll
                for (int o = 1; o <= 2; o <<= 1)
                    v = fmaxf(v, __shfl_xor_sync(~0u, v, o));
                pm[mt][hf] = v;
            }
        if (t == 0) {
#pragma unroll
            for (int mt = 0; mt < 2; ++mt)
#pragma unroll
                for (int hf = 0; hf < 2; ++hf)
                    redM[(wm + mt * 16 + g + hf * 8) * 4 + wcol] = pm[mt][hf];
        }
        __syncthreads();

        float fsc[2][2], mnew[2][2];
#pragma unroll
        for (int mt = 0; mt < 2; ++mt)
#pragma unroll
            for (int hf = 0; hf < 2; ++hf) {
                int r = wm + mt * 16 + g + hf * 8;
                float rm = fmaxf(fmaxf(redM[r * 4], redM[r * 4 + 1]),
                                 fmaxf(redM[r * 4 + 2], redM[r * 4 + 3])) * scale;
                float mn = fmaxf(m[mt][hf], rm);
                fsc[mt][hf] = __expf(m[mt][hf] - mn);
                mnew[mt][hf] = mn;
                m[mt][hf] = mn;
            }

        // rescale O, exponentiate S (-> P in sacc), partial row sums
        float psum[2][2];
#pragma unroll
        for (int mt = 0; mt < 2; ++mt)
#pragma unroll
            for (int hf = 0; hf < 2; ++hf) {
                float ssum = 0.f;
#pragma unroll
                for (int nt = 0; nt < 4; ++nt) {
                    oacc[mt][nt][hf * 2]     *= fsc[mt][hf];
                    oacc[mt][nt][hf * 2 + 1] *= fsc[mt][hf];
                    float p0 = __expf(sacc[mt][nt][hf * 2]     * scale - mnew[mt][hf]);
                    float p1 = __expf(sacc[mt][nt][hf * 2 + 1] * scale - mnew[mt][hf]);
                    sacc[mt][nt][hf * 2]     = p0;
                    sacc[mt][nt][hf * 2 + 1] = p1;
                    ssum += p0 + p1;
                }
#pragma unroll
                for (int o = 1; o <= 2; o <<= 1)
                    ssum += __shfl_xor_sync(~0u, ssum, o);
                psum[mt][hf] = ssum;
            }
        if (t == 0) {
#pragma unroll
            for (int mt = 0; mt < 2; ++mt)
#pragma unroll
                for (int hf = 0; hf < 2; ++hf)
                    redS[(wm + mt * 16 + g + hf * 8) * 4 + wcol] = psum[mt][hf];
        }
        __syncthreads();
#pragma unroll
        for (int mt = 0; mt < 2; ++mt)
#pragma unroll
            for (int hf = 0; hf < 2; ++hf) {
                int r = wm + mt * 16 + g + hf * 8;
                float rs = redS[r * 4] + redS[r * 4 + 1] + redS[r * 4 + 2] + redS[r * 4 + 3];
                l[mt][hf] = l[mt][hf] * fsc[mt][hf] + rs;
            }

        // ---- write P (hi/lo bf16) to smem ----
#pragma unroll
        for (int mt = 0; mt < 2; ++mt) {
            const int r1 = wm + mt * 16 + g;
#pragma unroll
            for (int nt = 0; nt < 4; ++nt) {
                const int colB = (wn + nt * 8 + t * 2) * 2;
                uint32_t a0 = smb + F_PHI + r1 * F_PITCHP + colB;
                uint32_t h0 = packbf(sacc[mt][nt][0], sacc[mt][nt][1]);
                uint32_t l0 = packbf(sacc[mt][nt][0] - lo_of(h0),
                                     sacc[mt][nt][1] - hi_of(h0));
                sts_u32(a0, h0);
                sts_u32(a0 + F_PLO_OF, l0);
                uint32_t a1 = a0 + 8 * F_PITCHP;
                uint32_t h1 = packbf(sacc[mt][nt][2], sacc[mt][nt][3]);
                uint32_t l1 = packbf(sacc[mt][nt][2] - lo_of(h1),
                                     sacc[mt][nt][3] - hi_of(h1));
                sts_u32(a1, h1);
                sts_u32(a1 + F_PLO_OF, l1);
            }
        }
        __syncthreads();

        // ---- PV phase: O += P · Vt^T, contraction 128 in 4 chunks of 32 ----
        const size_t vbase = ((size_t)z * DH + srow) * SS + (size_t)kb * 128 + scg;
        auto issueV = [&](int c) {
            const uint32_t dst = smb + (c & 1) * F_STAGE + srow * PITCH + scg * 2;
            cp16(dst,          vth + vbase + c * 32);
            cp16(dst + OF_ALO, vtl + vbase + c * 32);
        };

        auto COMPUTE_PV = [&](int s, int ch) {
            const uint32_t sa = smb + s * F_STAGE;
            const uint32_t pa = smb + F_PHI + ch * 64;
#pragma unroll
            for (int ks = 0; ks < 2; ++ks) {
                const uint32_t colb = ks * 32;
                uint32_t ahi[2][4], alo[2][4], bhi[2][4], blo[2][4];
#pragma unroll
                for (int mt = 0; mt < 2; ++mt) {
                    uint32_t addr = pa +
                        (wm + mt * 16 + (lane & 15)) * F_PITCHP + colb + (lane >> 4) * 16;
                    ldm_x4(addr, ahi[mt]);
                    ldm_x4(addr + F_PLO_OF, alo[mt]);
                }
#pragma unroll
                for (int np = 0; np < 2; ++np) {
                    uint32_t addr = sa +
                        (wn + np * 16 + (lane & 7) + ((lane >> 4) << 3)) * PITCH +
                        colb + ((lane >> 3) & 1) * 16;
                    ldm_x4(addr, bhi[np]);
                    ldm_x4(addr + OF_ALO, blo[np]);
                }
#pragma unroll
                for (int mt = 0; mt < 2; ++mt)
#pragma unroll
                    for (int nt = 0; nt < 4; ++nt) {
                        uint32_t b0h = bhi[nt >> 1][(nt & 1) * 2];
                        uint32_t b1h = bhi[nt >> 1][(nt & 1) * 2 + 1];
                        uint32_t b0l = blo[nt >> 1][(nt & 1) * 2];
                        uint32_t b1l = blo[nt >> 1][(nt & 1) * 2 + 1];
                        mma16816(oacc[mt][nt], ahi[mt], b0h, b1h);
                        mma16816(oacc[mt][nt], ahi[mt], b0l, b1l);
                        mma16816(oacc[mt][nt], alo[mt], b0h, b1h);
                    }
            }
        };

        issueV(0); CP_COMMIT;
        for (int c = 0; c < 4; ++c) {
            if (c < 3) { issueV(c + 1); CP_COMMIT; CP_WAIT1; } else { CP_WAIT0; }
            __syncthreads();
            COMPUTE_PV(c & 1, c);
            __syncthreads();
        }
    }

    // ---- final normalization + store ----
    float inv[2][2];
#pragma unroll
    for (int mt = 0; mt < 2; ++mt) {
        inv[mt][0] = 1.0f / l[mt][0];
        inv[mt][1] = 1.0f / l[mt][1];
    }
#pragma unroll
    for (int mt = 0; mt < 2; ++mt) {
        const long long r0 = (long long)(b * SS) + q0 + wm + mt * 16 + g;
#pragma unroll
        for (int nt = 0; nt < 4; ++nt) {
            const int col = h * DH + wn + nt * 8 + t * 2;
            float2 v0, v1;
            v0.x = oacc[mt][nt][0] * inv[mt][0];
            v0.y = oacc[mt][nt][1] * inv[mt][0];
            v1.x = oacc[mt][nt][2] * inv[mt][1];
            v1.y = oacc[mt][nt][3] * inv[mt][1];
            *(float2*)&att[r0 * HD + col] = v0;
            *(float2*)&att[(r0 + 8) * HD + col] = v1;
        }
    }
}

// ---------------------------------------------------------------------------

extern "C" void kernel_launch(void* const* d_in, const int* in_sizes, int n_in,
                              void* d_out, int out_size)
{
    const float* x    = (const float*)d_in[0];
    const float* fc   = (const float*)d_in[1];
    const float* fs   = (const float*)d_in[2];
    const float* w_lq = (const float*)d_in[3];
    const float* w_lkv= (const float*)d_in[4];
    const float* w_q  = (const float*)d_in[5];
    const float* w_k  = (const float*)d_in[6];
    const float* w_v  = (const float*)d_in[7];
    const float* w_qr = (const float*)d_in[8];
    const float* b_qr = (const float*)d_in[9];
    const float* w_kr = (const float*)d_in[10];
    const float* b_kr = (const float*)d_in[11];
    const float* w_o  = (const float*)d_in[12];
    const float* b_o  = (const float*)d_in[13];
    float* out = (float*)d_out;

    float *cq, *ckv, *qr, *kr, *vv, *att;
    __nv_bfloat16 *qah, *qal, *qrh, *qrl, *kah, *kal, *krh, *krl, *vth, *vtl;
    cudaGetSymbolAddress((void**)&cq,  g_cq);
    cudaGetSymbolAddress((void**)&ckv, g_ckv);
    cudaGetSymbolAddress((void**)&qr,  g_qr);
    cudaGetSymbolAddress((void**)&kr,  g_kr);
    cudaGetSymbolAddress((void**)&vv,  g_v);
    cudaGetSymbolAddress((void**)&att, g_att);
    cudaGetSymbolAddress((void**)&qah, g_qa_h);
    cudaGetSymbolAddress((void**)&qal, g_qa_l);
    cudaGetSymbolAddress((void**)&qrh, g_qr_h);
    cudaGetSymbolAddress((void**)&qrl, g_qr_l);
    cudaGetSymbolAddress((void**)&kah, g_ka_h);
    cudaGetSymbolAddress((void**)&kal, g_ka_l);
    cudaGetSymbolAddress((void**)&krh, g_kr_h);
    cudaGetSymbolAddress((void**)&krl, g_kr_l);
    cudaGetSymbolAddress((void**)&vth, g_vt_h);
    cudaGetSymbolAddress((void**)&vtl, g_vt_l);

    cudaFuncSetAttribute(tgemm<false, false, false>, cudaFuncAttributeMaxDynamicSharedMemorySize, SMEMSZ);
    cudaFuncSetAttribute(tgemm<true,  false, false>, cudaFuncAttributeMaxDynamicSharedMemorySize, SMEMSZ);
    cudaFuncSetAttribute(tgemm<false, false, true >, cudaFuncAttributeMaxDynamicSharedMemorySize, SMEMSZ);
    cudaFuncSetAttribute(flash_attn, cudaFuncAttributeMaxDynamicSharedMemorySize, F_SMEM);

    const float scale = 0.08838834764831845f; // 1/sqrt(128)

    // --- projections ---
    // cq = x @ w_lq^T (fp32)
    tgemm<false, false, false><<<dim3(LQ/128, MR/128, 1), 512, SMEMSZ>>>(
        DIM, x, DIM, 0, 0, w_lq, DIM, 0, 0, nullptr, nullptr,
        cq, LQ, 0, 0, nullptr, 1.f, 1, nullptr, nullptr);
    // ckv = x @ w_lkv^T (fp32)
    tgemm<false, false, false><<<dim3(LKV/128, MR/128, 1), 512, SMEMSZ>>>(
        DIM, x, DIM, 0, 0, w_lkv, DIM, 0, 0, nullptr, nullptr,
        ckv, LKV, 0, 0, nullptr, 1.f, 1, nullptr, nullptr);
    // qa = cq @ w_q^T -> split bf16
    tgemm<false, false, true><<<dim3(HD/128, MR/128, 1), 512, SMEMSZ>>>(
        LQ, cq, LQ, 0, 0, w_q, LQ, 0, 0, nullptr, nullptr,
        att, HD, 0, 0, nullptr, 1.f, 1, qah, qal);
    // qr = cq @ w_qr^T + b_qr (fp32, pre-rope)
    tgemm<true, false, false><<<dim3(HD/128, MR/128, 1), 512, SMEMSZ>>>(
        LQ, cq, LQ, 0, 0, w_qr, LQ, 0, 0, nullptr, nullptr,
        qr, HD, 0, 0, b_qr, 1.f, 1, nullptr, nullptr);
    // ka = ckv @ w_k^T -> split bf16
    tgemm<false, false, true><<<dim3(HD/128, MR/128, 1), 512, SMEMSZ>>>(
        LKV, ckv, LKV, 0, 0, w_k, LKV, 0, 0, nullptr, nullptr,
        att, HD, 0, 0, nullptr, 1.f, 1, kah, kal);
    // kr = x @ w_kr^T + b_kr (fp32, pre-rope)
    tgemm<true, false, false><<<dim3(HD/128, MR/128, 1), 512, SMEMSZ>>>(
        DIM, x, DIM, 0, 0, w_kr, DIM, 0, 0, nullptr, nullptr,
        kr, HD, 0, 0, b_kr, 1.f, 1, nullptr, nullptr);
    // v = ckv @ w_v^T (fp32)
    tgemm<false, false, false><<<dim3(HD/128, MR/128, 1), 512, SMEMSZ>>>(
        LKV, ckv, LKV, 0, 0, w_v, LKV, 0, 0, nullptr, nullptr,
        vv, HD, 0, 0, nullptr, 1.f, 1, nullptr, nullptr);

    // --- RoPE + split on qr, kr ---
    {
        long long pairs = (long long)MR * NH * (DH / 2);
        int blocks = (int)((pairs + 255) / 256);
        rope_split<<<blocks, 256>>>(qr, qrh, qrl, fc, fs);
        rope_split<<<blocks, 256>>>(kr, krh, krl, fc, fs);
    }

    // --- transpose V + split ---
    transpose_split<<<dim3(DH/32, SS/32, BB*NH), dim3(32, 8)>>>(vv, vth, vtl);

    // --- fused attention ---
    flash_attn<<<dim3(SS/128, BB*NH), 512, F_SMEM>>>(
        qah, qal, qrh, qrl, kah, kal, krh, krl, vth, vtl, att, scale);

    // --- out = att @ w_o^T + b_o ---
    tgemm<true, false, false><<<dim3(DIM/128, MR/128, 1), 512, SMEMSZ>>>(
        HD, att, HD, 0, 0, w_o, HD, 0, 0, nullptr, nullptr,
        out, DIM, 0, 0, b_o, 1.f, 1, nullptr, nullptr);

    (void)in_sizes; (void)n_in; (void)out_size;
}

// round 9
// speedup vs baseline: 1.4915x; 1.4915x over previous
#include <cuda_runtime.h>
#include <cuda_bf16.h>
#include <cstdint>

// Problem constants
#define BB   2
#define SS   2048
#define DIM  2048
#define NH   16
#define DH   128
#define LKV  512
#define LQ   1024
#define MR   (BB*SS)    // 4096
#define HD   (NH*DH)    // 2048

// fp32 scratch
__device__ float g_qr [MR*(size_t)HD];
__device__ float g_kr [MR*(size_t)HD];
__device__ float g_v  [MR*(size_t)HD];
__device__ float g_sc [(size_t)BB*NH*SS*SS];   // 512 MB scores

// bf16 hi/lo split buffers
__device__ __nv_bfloat16 g_x_h  [MR*(size_t)DIM],  g_x_l  [MR*(size_t)DIM];
__device__ __nv_bfloat16 g_wlq_h [(size_t)LQ*DIM],  g_wlq_l [(size_t)LQ*DIM];
__device__ __nv_bfloat16 g_wlkv_h[(size_t)LKV*DIM], g_wlkv_l[(size_t)LKV*DIM];
__device__ __nv_bfloat16 g_wq_h [(size_t)HD*LQ],   g_wq_l [(size_t)HD*LQ];
__device__ __nv_bfloat16 g_wqr_h[(size_t)HD*LQ],   g_wqr_l[(size_t)HD*LQ];
__device__ __nv_bfloat16 g_wk_h [(size_t)HD*LKV],  g_wk_l [(size_t)HD*LKV];
__device__ __nv_bfloat16 g_wv_h [(size_t)HD*LKV],  g_wv_l [(size_t)HD*LKV];
__device__ __nv_bfloat16 g_wkr_h[(size_t)HD*DIM],  g_wkr_l[(size_t)HD*DIM];
__device__ __nv_bfloat16 g_wo_h [(size_t)DIM*HD],  g_wo_l [(size_t)DIM*HD];
__device__ __nv_bfloat16 g_cq_h [MR*(size_t)LQ],   g_cq_l [MR*(size_t)LQ];
__device__ __nv_bfloat16 g_ckv_h[MR*(size_t)LKV],  g_ckv_l[MR*(size_t)LKV];
__device__ __nv_bfloat16 g_qa_h [MR*(size_t)HD],   g_qa_l [MR*(size_t)HD];
__device__ __nv_bfloat16 g_qrs_h[MR*(size_t)HD],   g_qrs_l[MR*(size_t)HD];
__device__ __nv_bfloat16 g_ka_h [MR*(size_t)HD],   g_ka_l [MR*(size_t)HD];
__device__ __nv_bfloat16 g_krs_h[MR*(size_t)HD],   g_krs_l[MR*(size_t)HD];
__device__ __nv_bfloat16 g_vt_h [(size_t)BB*NH*DH*SS], g_vt_l [(size_t)BB*NH*DH*SS];
__device__ __nv_bfloat16 g_p_h  [(size_t)BB*NH*SS*SS], g_p_l  [(size_t)BB*NH*SS*SS];
__device__ __nv_bfloat16 g_att_h[MR*(size_t)HD],   g_att_l[MR*(size_t)HD];

// ---------------------------------------------------------------------------
// Helpers
// ---------------------------------------------------------------------------
__device__ __forceinline__ uint32_t smem_u32(const void* p) {
    uint32_t a;
    asm("{ .reg .u64 t; cvta.to.shared.u64 t, %1; cvt.u32.u64 %0, t; }" : "=r"(a) : "l"(p));
    return a;
}
__device__ __forceinline__ void ldm_x4(uint32_t addr, uint32_t r[4]) {
    asm volatile("ldmatrix.sync.aligned.m8n8.x4.shared.b16 {%0,%1,%2,%3}, [%4];"
                 : "=r"(r[0]), "=r"(r[1]), "=r"(r[2]), "=r"(r[3]) : "r"(addr));
}
__device__ __forceinline__ void mma16816(float c[4], const uint32_t a[4],
                                         uint32_t b0, uint32_t b1) {
    asm volatile(
        "mma.sync.aligned.m16n8k16.row.col.f32.bf16.bf16.f32 "
        "{%0,%1,%2,%3}, {%4,%5,%6,%7}, {%8,%9}, {%0,%1,%2,%3};"
        : "+f"(c[0]), "+f"(c[1]), "+f"(c[2]), "+f"(c[3])
        : "r"(a[0]), "r"(a[1]), "r"(a[2]), "r"(a[3]), "r"(b0), "r"(b1));
}
__device__ __forceinline__ uint32_t packbf(float a, float b) {
    uint32_t r;
    asm("cvt.rn.satfinite.bf16x2.f32 %0, %1, %2;" : "=r"(r) : "f"(b), "f"(a));
    return r;
}
__device__ __forceinline__ float lo_of(uint32_t h) { return __uint_as_float(h << 16); }
__device__ __forceinline__ float hi_of(uint32_t h) { return __uint_as_float(h & 0xFFFF0000u); }

__device__ __forceinline__ void cp16(uint32_t dst, const void* src) {
    asm volatile("cp.async.cg.shared.global [%0], [%1], 16;" :: "r"(dst), "l"(src) : "memory");
}
#define CP_COMMIT asm volatile("cp.async.commit_group;" ::: "memory")
#define CP_WAIT0  asm volatile("cp.async.wait_group 0;" ::: "memory")
#define CP_WAIT1  asm volatile("cp.async.wait_group 1;" ::: "memory")

// SMEM: per stage A_hi, A_lo, B_hi, B_lo tiles: 128 rows x 80B pitch (64B data)
#define PITCH    80
#define OF_ALO   10240
#define OF_BHI   20480
#define OF_BLO   30720
#define STAGE_SZ 40960
#define NSTAGE   3
#define SMEMSZ   (NSTAGE*STAGE_SZ)     // 122880

// ---------------------------------------------------------------------------
// bgemm: C = alpha * A * B^T [+ bias], pre-split bf16 hi/lo inputs.
//   A: (Ah,Al) [M,K] bf16 row-major; B: (Bh,Bl) [N,K] bf16 row-major.
//   DUAL: continue accumulating A2 * B2^T (same shapes/strides).
//   SPLITOUT: write bf16 hi/lo (Chi,Clo) instead of fp32 C.
//   Batched via grid.z (z = zb*Hdiv + zh). 3-product fp32-accurate emulation.
//   Grid (N/128, M/128, Z), 512 threads, 3-stage cp.async pipeline.
// ---------------------------------------------------------------------------
template<bool BIAS, bool DUAL, bool SPLITOUT>
__global__ __launch_bounds__(512)
void bgemm(int K,
           const __nv_bfloat16* __restrict__ Ah, const __nv_bfloat16* __restrict__ Al,
           int lda, long long sAb, long long sAz,
           const __nv_bfloat16* __restrict__ Bh, const __nv_bfloat16* __restrict__ Bl,
           int ldb, long long sBb, long long sBz,
           const __nv_bfloat16* __restrict__ A2h, const __nv_bfloat16* __restrict__ A2l,
           const __nv_bfloat16* __restrict__ B2h, const __nv_bfloat16* __restrict__ B2l,
           float* __restrict__ C, int ldc, long long sCb, long long sCz,
           const float* __restrict__ bias, float alpha, int Hdiv,
           __nv_bfloat16* __restrict__ Chi, __nv_bfloat16* __restrict__ Clo)
{
    extern __shared__ __align__(128) char smc[];
    const uint32_t smb = smem_u32(smc);
    const int tid  = threadIdx.x;
    const int lane = tid & 31;
    const int wid  = tid >> 5;
    const int wm   = (wid & 3) * 32;
    const int wn   = (wid >> 2) * 32;

    int z = blockIdx.z;
    int zb = z / Hdiv, zh = z - zb * Hdiv;
    const long long offA = zb * sAb + zh * sAz;
    const long long offB = zb * sBb + zh * sBz;
    Ah += offA; Al += offA;
    Bh += offB; Bl += offB;
    if (DUAL) { A2h += offA; A2l += offA; B2h += offB; B2l += offB; }
    const long long offC = zb * sCb + zh * sCz;
    if (SPLITOUT) { Chi += offC; Clo += offC; }
    else          { C   += offC; }

    // staging: 512 threads cover 128 rows x 32 k, 8 bf16 (16B) per thread
    const int arow  = tid >> 2;
    const int aseg8 = (tid & 3) * 8;
    const long long aoff = (long long)(blockIdx.y * 128 + arow) * lda + aseg8;
    const long long boff = (long long)(blockIdx.x * 128 + arow) * ldb + aseg8;
    const uint32_t dstb = smb + arow * PITCH + aseg8 * 2;

    float acc[2][4][4];
#pragma unroll
    for (int i = 0; i < 2; i++)
#pragma unroll
        for (int j = 0; j < 4; j++)
#pragma unroll
            for (int k = 0; k < 4; k++) acc[i][j][k] = 0.f;

    const int nch   = K >> 5;
    const int total = DUAL ? nch * 2 : nch;

    auto issue = [&](int c) {
        const __nv_bfloat16 *ah = Ah, *al = Al, *bh = Bh, *bl = Bl;
        int cc = c;
        if (DUAL && c >= nch) { ah = A2h; al = A2l; bh = B2h; bl = B2l; cc = c - nch; }
        const long long ka = aoff + cc * 32;
        const long long kb = boff + cc * 32;
        const uint32_t dst = dstb + (c % NSTAGE) * STAGE_SZ;
        cp16(dst,          ah + ka);
        cp16(dst + OF_ALO, al + ka);
        cp16(dst + OF_BHI, bh + kb);
        cp16(dst + OF_BLO, bl + kb);
    };

    auto COMPUTE = [&](int s) {
        const uint32_t sa = smb + s * STAGE_SZ;
#pragma unroll
        for (int ks = 0; ks < 2; ++ks) {
            const uint32_t colb = ks * 32;
            uint32_t ahi[2][4], alo[2][4], bhi[2][4], blo[2][4];
#pragma unroll
            for (int mt = 0; mt < 2; ++mt) {
                uint32_t addr = sa +
                    (wm + mt * 16 + (lane & 15)) * PITCH + colb + (lane >> 4) * 16;
                ldm_x4(addr, ahi[mt]);
                ldm_x4(addr + OF_ALO, alo[mt]);
            }
#pragma unroll
            for (int np = 0; np < 2; ++np) {
                uint32_t addr = sa + OF_BHI +
                    (wn + np * 16 + (lane & 7) + ((lane >> 4) << 3)) * PITCH +
                    colb + ((lane >> 3) & 1) * 16;
                ldm_x4(addr, bhi[np]);
                ldm_x4(addr + (OF_BLO - OF_BHI), blo[np]);
            }
#pragma unroll
            for (int mt = 0; mt < 2; ++mt)
#pragma unroll
                for (int nt = 0; nt < 4; ++nt) {
                    uint32_t b0h = bhi[nt >> 1][(nt & 1) * 2];
                    uint32_t b1h = bhi[nt >> 1][(nt & 1) * 2 + 1];
                    uint32_t b0l = blo[nt >> 1][(nt & 1) * 2];
                    uint32_t b1l = blo[nt >> 1][(nt & 1) * 2 + 1];
                    mma16816(acc[mt][nt], ahi[mt], b0h, b1h);
                    mma16816(acc[mt][nt], ahi[mt], b0l, b1l);
                    mma16816(acc[mt][nt], alo[mt], b0h, b1h);
                }
        }
    };

    // 3-stage pipeline, one sync per chunk
    issue(0); CP_COMMIT;
    issue(1); CP_COMMIT;
    for (int c = 0; c < total; ++c) {
        if (c + 1 < total) { CP_WAIT1; } else { CP_WAIT0; }
        __syncthreads();
        COMPUTE(c % NSTAGE);
        if (c + 2 < total) { issue(c + 2); CP_COMMIT; }
    }

    // epilogue
    const int g = lane >> 2, t = lane & 3;
#pragma unroll
    for (int mt = 0; mt < 2; ++mt) {
        const int r0 = blockIdx.y * 128 + wm + mt * 16 + g;
#pragma unroll
        for (int nt = 0; nt < 4; ++nt) {
            const int col = blockIdx.x * 128 + wn + nt * 8 + t * 2;
            float b0 = 0.f, b1 = 0.f;
            if (BIAS) { b0 = bias[col]; b1 = bias[col + 1]; }
            float2 v0, v1;
            v0.x = alpha * acc[mt][nt][0] + b0;
            v0.y = alpha * acc[mt][nt][1] + b1;
            v1.x = alpha * acc[mt][nt][2] + b0;
            v1.y = alpha * acc[mt][nt][3] + b1;
            if (SPLITOUT) {
                uint32_t h0 = packbf(v0.x, v0.y);
                uint32_t l0 = packbf(v0.x - lo_of(h0), v0.y - hi_of(h0));
                uint32_t h1 = packbf(v1.x, v1.y);
                uint32_t l1 = packbf(v1.x - lo_of(h1), v1.y - hi_of(h1));
                *(uint32_t*)&Chi[(long long)r0 * ldc + col] = h0;
                *(uint32_t*)&Clo[(long long)r0 * ldc + col] = l0;
                *(uint32_t*)&Chi[(long long)(r0 + 8) * ldc + col] = h1;
                *(uint32_t*)&Clo[(long long)(r0 + 8) * ldc + col] = l1;
            } else {
                *(float2*)&C[(long long)r0 * ldc + col] = v0;
                *(float2*)&C[(long long)(r0 + 8) * ldc + col] = v1;
            }
        }
    }
}

// ---------------------------------------------------------------------------
// Split fp32 -> bf16 hi/lo, 9 jobs in one launch (grid.y selects job)
// ---------------------------------------------------------------------------
struct SplitJob  { const float* s; __nv_bfloat16* h; __nv_bfloat16* l; int n4; };
struct SplitJobs { SplitJob j[9]; };

__global__ void split_all(SplitJobs js)
{
    SplitJob job = js.j[blockIdx.y];
    int i = blockIdx.x * blockDim.x + threadIdx.x;
    if (i >= job.n4) return;
    float4 v = ((const float4*)job.s)[i];
    uint32_t h0 = packbf(v.x, v.y), h1 = packbf(v.z, v.w);
    uint32_t l0 = packbf(v.x - lo_of(h0), v.y - hi_of(h0));
    uint32_t l1 = packbf(v.z - lo_of(h1), v.w - hi_of(h1));
    ((uint2*)job.h)[i] = make_uint2(h0, h1);
    ((uint2*)job.l)[i] = make_uint2(l0, l1);
}

// ---------------------------------------------------------------------------
// RoPE + split: read fp32 [B*S, H*DH], rotate, write bf16 hi/lo
// ---------------------------------------------------------------------------
__global__ void rope_split(const float* __restrict__ src,
                           __nv_bfloat16* __restrict__ dh,
                           __nv_bfloat16* __restrict__ dl,
                           const float* __restrict__ fc,
                           const float* __restrict__ fs)
{
    long long idx = (long long)blockIdx.x * blockDim.x + threadIdx.x;
    const long long total = (long long)MR * NH * (DH / 2);
    if (idx >= total) return;
    int i = (int)(idx & 63);
    long long t2 = idx >> 6;
    int h = (int)(t2 % NH);
    long long row = t2 / NH;
    int s = (int)(row % SS);
    float c  = fc[s * 64 + i];
    float sn = fs[s * 64 + i];
    size_t off = (size_t)row * HD + h * DH + 2 * i;
    float e = src[off], o = src[off + 1];
    float e2 = e * c - o * sn;
    float o2 = e * sn + o * c;
    uint32_t hi = packbf(e2, o2);
    uint32_t lo = packbf(e2 - lo_of(hi), o2 - hi_of(hi));
    *(uint32_t*)&dh[off] = hi;
    *(uint32_t*)&dl[off] = lo;
}

// ---------------------------------------------------------------------------
// Transpose V + split: vt[z*DH + d][s] = v[(b*SS+s)*HD + h*DH + d]
// ---------------------------------------------------------------------------
__global__ void transpose_split(const float* __restrict__ v,
                                __nv_bfloat16* __restrict__ vth,
                                __nv_bfloat16* __restrict__ vtl)
{
    __shared__ float t[32][33];
    int z = blockIdx.z;
    int b = z / NH, h = z - b * NH;
    int s0 = blockIdx.y * 32, d0 = blockIdx.x * 32;
    int x = threadIdx.x, y = threadIdx.y;
#pragma unroll
    for (int i = 0; i < 32; i += 8)
        t[y + i][x] = v[((long long)(b * SS + s0 + y + i)) * HD + h * DH + d0 + x];
    __syncthreads();
#pragma unroll
    for (int i = 0; i < 32; i += 8) {
        float val = t[x][y + i];
        __nv_bfloat16 hb = __float2bfloat16(val);
        __nv_bfloat16 lb = __float2bfloat16(val - __bfloat162float(hb));
        size_t off = ((size_t)(z * DH + d0 + y + i)) * SS + s0 + x;
        vth[off] = hb;
        vtl[off] = lb;
    }
}

// ---------------------------------------------------------------------------
// Softmax + split: read fp32 score row (2048), write normalized P bf16 hi/lo.
// 256 threads, 4 float2 pairs per thread.
// ---------------------------------------------------------------------------
__global__ __launch_bounds__(256) void softmax_split(const float* __restrict__ S,
                                                     __nv_bfloat16* __restrict__ Ph,
                                                     __nv_bfloat16* __restrict__ Pl)
{
    const float* p = S + (long long)blockIdx.x * SS;
    uint32_t* oh = (uint32_t*)(Ph + (long long)blockIdx.x * SS);
    uint32_t* ol = (uint32_t*)(Pl + (long long)blockIdx.x * SS);
    const int t = threadIdx.x;
    __shared__ float red[8];

    float2 v[4];
#pragma unroll
    for (int j = 0; j < 4; ++j) v[j] = *(const float2*)&p[2 * t + 512 * j];

    float m = fmaxf(v[0].x, v[0].y);
#pragma unroll
    for (int j = 1; j < 4; ++j) m = fmaxf(m, fmaxf(v[j].x, v[j].y));
#pragma unroll
    for (int o = 16; o > 0; o >>= 1) m = fmaxf(m, __shfl_xor_sync(~0u, m, o));
    if ((t & 31) == 0) red[t >> 5] = m;
    __syncthreads();
    if (t < 32) {
        float mm = red[t & 7];
#pragma unroll
        for (int o = 4; o > 0; o >>= 1) mm = fmaxf(mm, __shfl_xor_sync(~0u, mm, o));
        if (t == 0) red[0] = mm;
    }
    __syncthreads();
    m = red[0];
    __syncthreads();

    float sum = 0.f;
#pragma unroll
    for (int j = 0; j < 4; ++j) {
        v[j].x = __expf(v[j].x - m);
        v[j].y = __expf(v[j].y - m);
        sum += v[j].x + v[j].y;
    }
#pragma unroll
    for (int o = 16; o > 0; o >>= 1) sum += __shfl_xor_sync(~0u, sum, o);
    if ((t & 31) == 0) red[t >> 5] = sum;
    __syncthreads();
    if (t < 32) {
        float ss = red[t & 7];
#pragma unroll
        for (int o = 4; o > 0; o >>= 1) ss += __shfl_xor_sync(~0u, ss, o);
        if (t == 0) red[0] = ss;
    }
    __syncthreads();
    const float inv = 1.0f / red[0];
#pragma unroll
    for (int j = 0; j < 4; ++j) {
        float p0 = v[j].x * inv, p1 = v[j].y * inv;
        uint32_t h = packbf(p0, p1);
        uint32_t l = packbf(p0 - lo_of(h), p1 - hi_of(h));
        oh[t + 256 * j] = h;
        ol[t + 256 * j] = l;
    }
}

// ---------------------------------------------------------------------------

extern "C" void kernel_launch(void* const* d_in, const int* in_sizes, int n_in,
                              void* d_out, int out_size)
{
    const float* x    = (const float*)d_in[0];
    const float* fc   = (const float*)d_in[1];
    const float* fs   = (const float*)d_in[2];
    const float* w_lq = (const float*)d_in[3];
    const float* w_lkv= (const float*)d_in[4];
    const float* w_q  = (const float*)d_in[5];
    const float* w_k  = (const float*)d_in[6];
    const float* w_v  = (const float*)d_in[7];
    const float* w_qr = (const float*)d_in[8];
    const float* b_qr = (const float*)d_in[9];
    const float* w_kr = (const float*)d_in[10];
    const float* b_kr = (const float*)d_in[11];
    const float* w_o  = (const float*)d_in[12];
    const float* b_o  = (const float*)d_in[13];
    float* out = (float*)d_out;

    float *qr, *kr, *vv, *sc;
    cudaGetSymbolAddress((void**)&qr, g_qr);
    cudaGetSymbolAddress((void**)&kr, g_kr);
    cudaGetSymbolAddress((void**)&vv, g_v);
    cudaGetSymbolAddress((void**)&sc, g_sc);

    __nv_bfloat16 *xh, *xl, *wlqh, *wlql, *wlkvh, *wlkvl, *wqh, *wql, *wqrh, *wqrl;
    __nv_bfloat16 *wkh, *wkl, *wvh, *wvl, *wkrh, *wkrl, *woh, *wol;
    __nv_bfloat16 *cqh, *cql, *ckvh, *ckvl, *qah, *qal, *qrh, *qrl, *kah, *kal;
    __nv_bfloat16 *krh, *krl, *vth, *vtl, *ph, *pl, *atth, *attl;
    cudaGetSymbolAddress((void**)&xh,    g_x_h);   cudaGetSymbolAddress((void**)&xl,    g_x_l);
    cudaGetSymbolAddress((void**)&wlqh,  g_wlq_h); cudaGetSymbolAddress((void**)&wlql,  g_wlq_l);
    cudaGetSymbolAddress((void**)&wlkvh, g_wlkv_h);cudaGetSymbolAddress((void**)&wlkvl, g_wlkv_l);
    cudaGetSymbolAddress((void**)&wqh,   g_wq_h);  cudaGetSymbolAddress((void**)&wql,   g_wq_l);
    cudaGetSymbolAddress((void**)&wqrh,  g_wqr_h); cudaGetSymbolAddress((void**)&wqrl,  g_wqr_l);
    cudaGetSymbolAddress((void**)&wkh,   g_wk_h);  cudaGetSymbolAddress((void**)&wkl,   g_wk_l);
    cudaGetSymbolAddress((void**)&wvh,   g_wv_h);  cudaGetSymbolAddress((void**)&wvl,   g_wv_l);
    cudaGetSymbolAddress((void**)&wkrh,  g_wkr_h); cudaGetSymbolAddress((void**)&wkrl,  g_wkr_l);
    cudaGetSymbolAddress((void**)&woh,   g_wo_h);  cudaGetSymbolAddress((void**)&wol,   g_wo_l);
    cudaGetSymbolAddress((void**)&cqh,   g_cq_h);  cudaGetSymbolAddress((void**)&cql,   g_cq_l);
    cudaGetSymbolAddress((void**)&ckvh,  g_ckv_h); cudaGetSymbolAddress((void**)&ckvl,  g_ckv_l);
    cudaGetSymbolAddress((void**)&qah,   g_qa_h);  cudaGetSymbolAddress((void**)&qal,   g_qa_l);
    cudaGetSymbolAddress((void**)&qrh,   g_qrs_h); cudaGetSymbolAddress((void**)&qrl,   g_qrs_l);
    cudaGetSymbolAddress((void**)&kah,   g_ka_h);  cudaGetSymbolAddress((void**)&kal,   g_ka_l);
    cudaGetSymbolAddress((void**)&krh,   g_krs_h); cudaGetSymbolAddress((void**)&krl,   g_krs_l);
    cudaGetSymbolAddress((void**)&vth,   g_vt_h);  cudaGetSymbolAddress((void**)&vtl,   g_vt_l);
    cudaGetSymbolAddress((void**)&ph,    g_p_h);   cudaGetSymbolAddress((void**)&pl,    g_p_l);
    cudaGetSymbolAddress((void**)&atth,  g_att_h); cudaGetSymbolAddress((void**)&attl,  g_att_l);

    cudaFuncSetAttribute(bgemm<false, false, true >, cudaFuncAttributeMaxDynamicSharedMemorySize, SMEMSZ);
    cudaFuncSetAttribute(bgemm<true,  false, false>, cudaFuncAttributeMaxDynamicSharedMemorySize, SMEMSZ);
    cudaFuncSetAttribute(bgemm<false, true,  false>, cudaFuncAttributeMaxDynamicSharedMemorySize, SMEMSZ);
    cudaFuncSetAttribute(bgemm<false, false, false>, cudaFuncAttributeMaxDynamicSharedMemorySize, SMEMSZ);

    const float scale = 0.08838834764831845f; // 1/sqrt(128)

    // --- split x + all weights (one launch) ---
    {
        SplitJobs js;
        js.j[0] = { x,     xh,    xl,    MR*DIM/4 };
        js.j[1] = { w_lq,  wlqh,  wlql,  LQ*DIM/4 };
        js.j[2] = { w_lkv, wlkvh, wlkvl, LKV*DIM/4 };
        js.j[3] = { w_q,   wqh,   wql,   HD*LQ/4 };
        js.j[4] = { w_qr,  wqrh,  wqrl,  HD*LQ/4 };
        js.j[5] = { w_k,   wkh,   wkl,   HD*LKV/4 };
        js.j[6] = { w_v,   wvh,   wvl,   HD*LKV/4 };
        js.j[7] = { w_kr,  wkrh,  wkrl,  HD*DIM/4 };
        js.j[8] = { w_o,   woh,   wol,   DIM*HD/4 };
        split_all<<<dim3((MR*DIM/4 + 255)/256, 9), 256>>>(js);
    }

    // --- projections ---
    // cq = x @ w_lq^T -> split
    bgemm<false, false, true><<<dim3(LQ/128, MR/128, 1), 512, SMEMSZ>>>(
        DIM, xh, xl, DIM, 0, 0, wlqh, wlql, DIM, 0, 0,
        nullptr, nullptr, nullptr, nullptr,
        nullptr, LQ, 0, 0, nullptr, 1.f, 1, cqh, cql);
    // ckv = x @ w_lkv^T -> split
    bgemm<false, false, true><<<dim3(LKV/128, MR/128, 1), 512, SMEMSZ>>>(
        DIM, xh, xl, DIM, 0, 0, wlkvh, wlkvl, DIM, 0, 0,
        nullptr, nullptr, nullptr, nullptr,
        nullptr, LKV, 0, 0, nullptr, 1.f, 1, ckvh, ckvl);
    // qa = cq @ w_q^T -> split
    bgemm<false, false, true><<<dim3(HD/128, MR/128, 1), 512, SMEMSZ>>>(
        LQ, cqh, cql, LQ, 0, 0, wqh, wql, LQ, 0, 0,
        nullptr, nullptr, nullptr, nullptr,
        nullptr, HD, 0, 0, nullptr, 1.f, 1, qah, qal);
    // qr = cq @ w_qr^T + b_qr -> fp32 (pre-rope)
    bgemm<true, false, false><<<dim3(HD/128, MR/128, 1), 512, SMEMSZ>>>(
        LQ, cqh, cql, LQ, 0, 0, wqrh, wqrl, LQ, 0, 0,
        nullptr, nullptr, nullptr, nullptr,
        qr, HD, 0, 0, b_qr, 1.f, 1, nullptr, nullptr);
    // ka = ckv @ w_k^T -> split
    bgemm<false, false, true><<<dim3(HD/128, MR/128, 1), 512, SMEMSZ>>>(
        LKV, ckvh, ckvl, LKV, 0, 0, wkh, wkl, LKV, 0, 0,
        nullptr, nullptr, nullptr, nullptr,
        nullptr, HD, 0, 0, nullptr, 1.f, 1, kah, kal);
    // kr = x @ w_kr^T + b_kr -> fp32 (pre-rope)
    bgemm<true, false, false><<<dim3(HD/128, MR/128, 1), 512, SMEMSZ>>>(
        DIM, xh, xl, DIM, 0, 0, wkrh, wkrl, DIM, 0, 0,
        nullptr, nullptr, nullptr, nullptr,
        kr, HD, 0, 0, b_kr, 1.f, 1, nullptr, nullptr);
    // v = ckv @ w_v^T -> fp32
    bgemm<false, false, false><<<dim3(HD/128, MR/128, 1), 512, SMEMSZ>>>(
        LKV, ckvh, ckvl, LKV, 0, 0, wvh, wvl, LKV, 0, 0,
        nullptr, nullptr, nullptr, nullptr,
        vv, HD, 0, 0, nullptr, 1.f, 1, nullptr, nullptr);

    // --- RoPE + split on qr, kr ---
    {
        long long pairs = (long long)MR * NH * (DH / 2);
        int blocks = (int)((pairs + 255) / 256);
        rope_split<<<blocks, 256>>>(qr, qrh, qrl, fc, fs);
        rope_split<<<blocks, 256>>>(kr, krh, krl, fc, fs);
    }

    // --- transpose V + split ---
    transpose_split<<<dim3(DH/32, SS/32, BB*NH), dim3(32, 8)>>>(vv, vth, vtl);

    // --- scores: sc[z] = (qa.ka^T + qr.kr^T) * scale ---
    {
        long long sQb = (long long)SS * HD;
        long long sQz = DH;
        long long sSb = (long long)NH * SS * SS;
        long long sSz = (long long)SS * SS;
        bgemm<false, true, false><<<dim3(SS/128, SS/128, BB*NH), 512, SMEMSZ>>>(
            DH, qah, qal, HD, sQb, sQz, kah, kal, HD, sQb, sQz,
            qrh, qrl, krh, krl,
            sc, SS, sSb, sSz, nullptr, scale, NH, nullptr, nullptr);
    }

    // --- softmax + split -> P hi/lo ---
    softmax_split<<<BB * NH * SS, 256>>>(sc, ph, pl);

    // --- PV: att = P @ vt^T -> split ---
    {
        long long sPb = (long long)NH * SS * SS;
        long long sPz = (long long)SS * SS;
        long long sVb = (long long)NH * DH * SS;
        long long sVz = (long long)DH * SS;
        long long sCb = (long long)SS * HD;
        long long sCz = DH;
        bgemm<false, false, true><<<dim3(DH/128, SS/128, BB*NH), 512, SMEMSZ>>>(
            SS, ph, pl, SS, sPb, sPz, vth, vtl, SS, sVb, sVz,
            nullptr, nullptr, nullptr, nullptr,
            nullptr, HD, sCb, sCz, nullptr, 1.f, NH, atth, attl);
    }

    // --- out = att @ w_o^T + b_o ---
    bgemm<true, false, false><<<dim3(DIM/128, MR/128, 1), 512, SMEMSZ>>>(
        HD, atth, attl, HD, 0, 0, woh, wol, HD, 0, 0,
        nullptr, nullptr, nullptr, nullptr,
        out, DIM, 0, 0, b_o, 1.f, 1, nullptr, nullptr);

    (void)in_sizes; (void)n_in; (void)out_size;
}